// round 5
// baseline (speedup 1.0000x reference)
#include <cuda_runtime.h>
#include <math.h>

#define NN 169343
#define DIN 128
#define DH 256
#define DOUTF 40
#define EPSV 1e-5f

// ---------------- scratch (static device globals) ----------------
__device__ __align__(128) float g_dinv[NN];
__device__ __align__(128) float g_selfn[NN];
__device__ __align__(128) float g_z[(size_t)NN * DH];     // aggregation buffer (L1: Nx128, L2: Nx256)
__device__ __align__(128) float g_h[(size_t)NN * DH];     // hidden activations
__device__ __align__(128) float g_z3[(size_t)NN * DOUTF]; // h2 @ W3

// ---------------- degree / norm ----------------
__global__ void k_init_deg(float* __restrict__ deg, int n) {
    int i = blockIdx.x * blockDim.x + threadIdx.x;
    if (i < n) deg[i] = 1.0f;  // self loop
}

__global__ void k_count_deg(const int* __restrict__ dst, int E, float* __restrict__ deg) {
    int e = blockIdx.x * blockDim.x + threadIdx.x;
    if (e < E) atomicAdd(&deg[dst[e]], 1.0f);
}

__global__ void k_norms(const float* __restrict__ deg, float* __restrict__ dinv,
                        float* __restrict__ selfn, int n) {
    int i = blockIdx.x * blockDim.x + threadIdx.x;
    if (i < n) {
        float r = rsqrtf(deg[i]);
        dinv[i] = r;
        selfn[i] = r * r;
    }
}

// ---------------- row scale (+ optional per-col bias): z = x * selfn[row] (+ bias[col]) ----------------
__global__ void k_scale_rows(const float4* __restrict__ x, const float* __restrict__ selfn,
                             const float4* __restrict__ bias4, float4* __restrict__ z,
                             int n, int Fv) {
    int idx = blockIdx.x * blockDim.x + threadIdx.x;
    if (idx >= n * Fv) return;
    int r = idx / Fv;
    int c = idx - r * Fv;
    float s = selfn[r];
    float4 v = x[idx];
    v.x *= s; v.y *= s; v.z *= s; v.w *= s;
    if (bias4) {
        float4 b = bias4[c];
        v.x += b.x; v.y += b.y; v.z += b.z; v.w += b.w;
    }
    z[idx] = v;
}

// ---------------- edge scatter: agg[dst] += feat[src] * dinv[src]*dinv[dst] ----------------
template <int F>
__global__ void k_scatter(const float* __restrict__ feat, float* __restrict__ agg,
                          const int* __restrict__ src, const int* __restrict__ dst,
                          int E, const float* __restrict__ dinv) {
    constexpr int VPE = F / 4;  // float4 slots per edge
    long long gid = (long long)blockIdx.x * blockDim.x + threadIdx.x;
    long long total = (long long)E * VPE;
    if (gid >= total) return;
    int e = (int)(gid / VPE);
    int i = (int)(gid - (long long)e * VPE);
    int s = src[e];
    int d = dst[e];
    float w = dinv[s] * dinv[d];
    float4 v = __ldg((const float4*)(feat + (size_t)s * F) + i);
    float* p = agg + (size_t)d * F + (size_t)i * 4;
    atomicAdd(p + 0, v.x * w);
    atomicAdd(p + 1, v.y * w);
    atomicAdd(p + 2, v.z * w);
    atomicAdd(p + 3, v.w * w);
}

// ---------------- tiled fp32 GEMM with fused bias (+ optional BN + ReLU, + optional dual store) ----
__global__ __launch_bounds__(256) void k_gemm_fused(
    const float* __restrict__ A, const float* __restrict__ B, float* __restrict__ C,
    float* __restrict__ C2,
    int M, int K, int Nc,
    const float* __restrict__ bias,
    const float* __restrict__ gamma, const float* __restrict__ beta,
    const float* __restrict__ mean, const float* __restrict__ var,
    int bn_relu) {
    constexpr int BM = 128, BN = 64, BK = 16;
    __shared__ float As[BK][BM];
    __shared__ float Bs[BK][BN];

    int tid = threadIdx.x;
    int tx = tid & 15;   // 16 cols * 4 = 64
    int ty = tid >> 4;   // 16 rows * 8 = 128
    int row0 = blockIdx.y * BM;
    int col0 = blockIdx.x * BN;

    float acc[8][4];
#pragma unroll
    for (int i = 0; i < 8; i++)
#pragma unroll
        for (int j = 0; j < 4; j++) acc[i][j] = 0.0f;

    for (int k0 = 0; k0 < K; k0 += BK) {
#pragma unroll
        for (int l = 0; l < 2; l++) {
            int f4 = tid + l * 256;
            int ar = f4 >> 2;
            int ac = (f4 & 3) * 4;
            float4 av = make_float4(0.f, 0.f, 0.f, 0.f);
            int gr = row0 + ar;
            if (gr < M) av = *(const float4*)&A[(size_t)gr * K + k0 + ac];
            As[ac + 0][ar] = av.x;
            As[ac + 1][ar] = av.y;
            As[ac + 2][ar] = av.z;
            As[ac + 3][ar] = av.w;
        }
        {
            int br = tid >> 4;
            int bc = (tid & 15) * 4;
            float4 bv = make_float4(0.f, 0.f, 0.f, 0.f);
            int gc = col0 + bc;
            if (gc < Nc) bv = *(const float4*)&B[(size_t)(k0 + br) * Nc + gc];
            Bs[br][bc + 0] = bv.x;
            Bs[br][bc + 1] = bv.y;
            Bs[br][bc + 2] = bv.z;
            Bs[br][bc + 3] = bv.w;
        }
        __syncthreads();

#pragma unroll
        for (int k = 0; k < BK; k++) {
            float4 a0 = *(const float4*)&As[k][ty * 8];
            float4 a1 = *(const float4*)&As[k][ty * 8 + 4];
            float4 b0 = *(const float4*)&Bs[k][tx * 4];
            float ar[8] = {a0.x, a0.y, a0.z, a0.w, a1.x, a1.y, a1.z, a1.w};
            float br[4] = {b0.x, b0.y, b0.z, b0.w};
#pragma unroll
            for (int i = 0; i < 8; i++)
#pragma unroll
                for (int j = 0; j < 4; j++) acc[i][j] = fmaf(ar[i], br[j], acc[i][j]);
        }
        __syncthreads();
    }

#pragma unroll
    for (int j = 0; j < 4; j++) {
        int c = col0 + tx * 4 + j;
        if (c >= Nc) continue;
        float bb = bias ? bias[c] : 0.0f;
        float sc = 1.0f, sh = 0.0f;
        if (bn_relu) {
            sc = rsqrtf(var[c] + EPSV) * gamma[c];
            sh = beta[c] - mean[c] * sc;
        }
#pragma unroll
        for (int i = 0; i < 8; i++) {
            int r = row0 + ty * 8 + i;
            if (r >= M) continue;
            float v = acc[i][j] + bb;
            if (bn_relu) v = fmaxf(0.0f, fmaf(v, sc, sh));
            C[(size_t)r * Nc + c] = v;
            if (C2) C2[(size_t)r * Nc + c] = v;
        }
    }
}

// ---------------- log_softmax over 40 cols, one warp per row (in-place safe) ----------------
__global__ void k_log_softmax40(const float* __restrict__ in, float* __restrict__ out, int n) {
    int warp = (blockIdx.x * blockDim.x + threadIdx.x) >> 5;
    int lane = threadIdx.x & 31;
    if (warp >= n) return;
    const float* p = in + (size_t)warp * DOUTF;
    float a = p[lane];
    float b = (lane < 8) ? p[32 + lane] : -3.402823e38f;
    float m = fmaxf(a, b);
#pragma unroll
    for (int o = 16; o; o >>= 1) m = fmaxf(m, __shfl_xor_sync(0xffffffffu, m, o));
    float s = expf(a - m) + ((lane < 8) ? expf(b - m) : 0.0f);
#pragma unroll
    for (int o = 16; o; o >>= 1) s += __shfl_xor_sync(0xffffffffu, s, o);
    float lse = m + logf(s);
    float* q = out + (size_t)warp * DOUTF;
    q[lane] = a - lse;
    if (lane < 8) q[32 + lane] = b - lse;
}

// ---------------- launch ----------------
static inline int cdiv(long long a, long long b) { return (int)((a + b - 1) / b); }

extern "C" void kernel_launch(void* const* d_in, const int* in_sizes, int n_in,
                              void* d_out, int out_size) {
    const float* x = (const float*)d_in[0];
    const int* ei = (const int*)d_in[1];      // int32 (JAX default disables x64)
    const float* W1 = (const float*)d_in[2];
    const float* b1 = (const float*)d_in[3];
    const float* g1 = (const float*)d_in[4];
    const float* be1 = (const float*)d_in[5];
    const float* m1 = (const float*)d_in[6];
    const float* v1 = (const float*)d_in[7];
    const float* W2 = (const float*)d_in[8];
    const float* b2 = (const float*)d_in[9];
    const float* g2 = (const float*)d_in[10];
    const float* be2 = (const float*)d_in[11];
    const float* m2 = (const float*)d_in[12];
    const float* v2 = (const float*)d_in[13];
    const float* W3 = (const float*)d_in[14];
    const float* b3 = (const float*)d_in[15];
    const int E = in_sizes[1] / 2;
    const int* src = ei;
    const int* dst = ei + E;

    float* out = (float*)d_out;                       // NN x 40 region
    const bool have_emb = out_size >= NN * (DOUTF + DH);
    float* emb = out + (size_t)NN * DOUTF;            // NN x 256 region (if present)

    float *dinv, *selfn, *zbuf, *h, *z3;
    cudaGetSymbolAddress((void**)&dinv, g_dinv);
    cudaGetSymbolAddress((void**)&selfn, g_selfn);
    cudaGetSymbolAddress((void**)&zbuf, g_z);
    cudaGetSymbolAddress((void**)&h, g_h);
    cudaGetSymbolAddress((void**)&z3, g_z3);

    float* deg = out;  // first NN floats of out region (consumed before L3)

    const int T = 256;

    // degrees + norms (deg = 1 + in-degree)
    k_init_deg<<<cdiv(NN, T), T>>>(deg, NN);
    k_count_deg<<<cdiv(E, T), T>>>(dst, E, deg);
    k_norms<<<cdiv(NN, T), T>>>(deg, dinv, selfn, NN);

    // ---- layer 1: z1 = Agg(x) [N,128]; h1 = relu(bn1(z1 @ W1 + b1)) ----
    k_scale_rows<<<cdiv((long long)NN * (DIN / 4), T), T>>>(
        (const float4*)x, selfn, nullptr, (float4*)zbuf, NN, DIN / 4);
    k_scatter<DIN><<<cdiv((long long)E * (DIN / 4), T), T>>>(x, zbuf, src, dst, E, dinv);
    {
        dim3 grid((DH + 63) / 64, (NN + 127) / 128);
        k_gemm_fused<<<grid, 256>>>(zbuf, W1, h, nullptr, NN, DIN, DH, b1, g1, be1, m1, v1, 1);
    }

    // ---- layer 2: z2 = Agg(h1) [N,256]; h2 = relu(bn2(z2 @ W2 + b2)) ----
    k_scale_rows<<<cdiv((long long)NN * (DH / 4), T), T>>>(
        (const float4*)h, selfn, nullptr, (float4*)zbuf, NN, DH / 4);
    k_scatter<DH><<<cdiv((long long)E * (DH / 4), T), T>>>(h, zbuf, src, dst, E, dinv);
    {
        // C = g_h (input for layer 3), C2 = emb (final embedding output); no aliasing with A=zbuf
        dim3 grid((DH + 63) / 64, (NN + 127) / 128);
        k_gemm_fused<<<grid, 256>>>(zbuf, W2, h, have_emb ? emb : nullptr,
                                    NN, DH, DH, b2, g2, be2, m2, v2, 1);
    }

    // ---- layer 3: z3 = h2 @ W3 [N,40]; out = log_softmax(Agg(z3) + b3) ----
    {
        dim3 grid((DOUTF + 63) / 64, (NN + 127) / 128);
        k_gemm_fused<<<grid, 256>>>(h, W3, z3, nullptr, NN, DH, DOUTF,
                                    nullptr, nullptr, nullptr, nullptr, nullptr, 0);
    }
    // out region: deg already consumed; reuse for L3 aggregation then softmax in place
    k_scale_rows<<<cdiv((long long)NN * (DOUTF / 4), T), T>>>(
        (const float4*)z3, selfn, (const float4*)b3, (float4*)out, NN, DOUTF / 4);
    k_scatter<DOUTF><<<cdiv((long long)E * (DOUTF / 4), T), T>>>(z3, out, src, dst, E, dinv);
    k_log_softmax40<<<cdiv((long long)NN * 32, T), T>>>(out, out, NN);
}

// round 6
// speedup vs baseline: 1.2814x; 1.2814x over previous
#include <cuda_runtime.h>
#include <math.h>

#define NN 169343
#define DIN 128
#define DH 256
#define DOUTF 40
#define EPSV 1e-5f
#define EMAX 2500000
#define NB_SCAN ((NN + 1023) / 1024)

// ---------------- scratch (static device globals) ----------------
__device__ __align__(128) float g_dinv[NN];
__device__ __align__(128) float g_selfn[NN];
__device__ __align__(128) int   g_cnt[NN];
__device__ __align__(128) int   g_cur[NN];
__device__ __align__(128) int   g_off[NN + 1];
__device__ __align__(128) int   g_blk[256];
__device__ __align__(128) int   g_csr_src[EMAX];
__device__ __align__(128) float g_csr_w[EMAX];
__device__ __align__(128) float g_z[(size_t)NN * DH];     // aggregation buffer
__device__ __align__(128) float g_h[(size_t)NN * DH];     // hidden activations
__device__ __align__(128) float g_z3[(size_t)NN * DOUTF]; // h2 @ W3

// ---------------- CSR construction ----------------
__global__ void k_zero_int(int* __restrict__ p, int n) {
    int i = blockIdx.x * blockDim.x + threadIdx.x;
    if (i < n) p[i] = 0;
}

__global__ void k_count_int(const int* __restrict__ dst, int E, int* __restrict__ cnt) {
    int e = blockIdx.x * blockDim.x + threadIdx.x;
    if (e < E) atomicAdd(&cnt[dst[e]], 1);
}

__global__ void k_norms_from_cnt(const int* __restrict__ cnt, float* __restrict__ dinv,
                                 float* __restrict__ selfn, int n) {
    int i = blockIdx.x * blockDim.x + threadIdx.x;
    if (i < n) {
        float deg = (float)cnt[i] + 1.0f;
        dinv[i] = rsqrtf(deg);
        selfn[i] = 1.0f / deg;
    }
}

// block-wise exclusive scan (1024 elems / block)
__global__ __launch_bounds__(1024) void k_scan_block(const int* __restrict__ cnt,
                                                     int* __restrict__ off,
                                                     int* __restrict__ blk, int n) {
    __shared__ int s[1024];
    int t = threadIdx.x;
    int i = blockIdx.x * 1024 + t;
    int v = (i < n) ? cnt[i] : 0;
    s[t] = v;
    __syncthreads();
#pragma unroll
    for (int o = 1; o < 1024; o <<= 1) {
        int add = (t >= o) ? s[t - o] : 0;
        __syncthreads();
        s[t] += add;
        __syncthreads();
    }
    if (i <= n) off[i] = s[t] - v;  // exclusive within block
    if (t == 1023) blk[blockIdx.x] = s[1023];
}

__global__ void k_scan_top(int* __restrict__ blk, int nb) {
    if (threadIdx.x == 0 && blockIdx.x == 0) {
        int run = 0;
        for (int b = 0; b < nb; b++) {
            int v = blk[b];
            blk[b] = run;
            run += v;
        }
    }
}

__global__ void k_scan_add(int* __restrict__ off, const int* __restrict__ blk, int n, int E) {
    int i = blockIdx.x * blockDim.x + threadIdx.x;
    if (i < n) off[i] += blk[i / 1024];
    if (i == 0) off[n] = E;
}

__global__ void k_fill(const int* __restrict__ src, const int* __restrict__ dst, int E,
                       const int* __restrict__ off, int* __restrict__ cur,
                       const float* __restrict__ dinv,
                       int* __restrict__ csr_src, float* __restrict__ csr_w) {
    int e = blockIdx.x * blockDim.x + threadIdx.x;
    if (e >= E) return;
    int d = dst[e];
    int s = src[e];
    int pos = off[d] + atomicAdd(&cur[d], 1);
    csr_src[pos] = s;
    csr_w[pos] = dinv[s];
}

// ---------------- CSR gather: agg[n] = dinv[n]*sum_e w_e*feat[src_e] + selfn[n]*feat[n] ----------------
// one block per node, F threads (F = 128 or 256)
template <int F>
__global__ __launch_bounds__(F) void k_gather(const float* __restrict__ feat,
                                              float* __restrict__ aggout,
                                              const int* __restrict__ off,
                                              const int* __restrict__ csr_src,
                                              const float* __restrict__ csr_w,
                                              const float* __restrict__ dinv,
                                              const float* __restrict__ selfn) {
    int node = blockIdx.x;
    int t = threadIdx.x;
    int beg = off[node], end = off[node + 1];
    float a0 = 0.f, a1 = 0.f, a2 = 0.f, a3 = 0.f;
    int e = beg;
    for (; e + 3 < end; e += 4) {
        int s0 = csr_src[e], s1 = csr_src[e + 1], s2 = csr_src[e + 2], s3 = csr_src[e + 3];
        float w0 = csr_w[e], w1 = csr_w[e + 1], w2 = csr_w[e + 2], w3 = csr_w[e + 3];
        a0 = fmaf(w0, __ldg(feat + (size_t)s0 * F + t), a0);
        a1 = fmaf(w1, __ldg(feat + (size_t)s1 * F + t), a1);
        a2 = fmaf(w2, __ldg(feat + (size_t)s2 * F + t), a2);
        a3 = fmaf(w3, __ldg(feat + (size_t)s3 * F + t), a3);
    }
    for (; e < end; e++)
        a0 = fmaf(csr_w[e], __ldg(feat + (size_t)csr_src[e] * F + t), a0);
    float acc = (a0 + a1) + (a2 + a3);
    float self = feat[(size_t)node * F + t];
    aggout[(size_t)node * F + t] = fmaf(dinv[node], acc, selfn[node] * self);
}

// ---------------- fused layer-3 gather (+bias) + log_softmax, one warp per node ----------------
__global__ __launch_bounds__(256) void k_gather40_softmax(
    const float* __restrict__ z3, const float* __restrict__ b3,
    float* __restrict__ out,
    const int* __restrict__ off, const int* __restrict__ csr_src,
    const float* __restrict__ csr_w,
    const float* __restrict__ dinv, const float* __restrict__ selfn) {
    int node = blockIdx.x * 8 + (threadIdx.x >> 5);
    int lane = threadIdx.x & 31;
    if (node >= NN) return;
    int beg = off[node], end = off[node + 1];
    float aa = 0.f, ab = 0.f;
    for (int e = beg; e < end; e++) {
        int s = csr_src[e];
        float w = csr_w[e];
        const float* fs = z3 + (size_t)s * DOUTF;
        aa = fmaf(w, fs[lane], aa);
        if (lane < 8) ab = fmaf(w, fs[32 + lane], ab);
    }
    float di = dinv[node], sn = selfn[node];
    const float* fz = z3 + (size_t)node * DOUTF;
    float a = fmaf(di, aa, fmaf(sn, fz[lane], b3[lane]));
    float b = (lane < 8) ? fmaf(di, ab, fmaf(sn, fz[32 + lane], b3[32 + lane])) : -3.402823e38f;
    // log_softmax over 40
    float m = fmaxf(a, b);
#pragma unroll
    for (int o = 16; o; o >>= 1) m = fmaxf(m, __shfl_xor_sync(0xffffffffu, m, o));
    float s = expf(a - m) + ((lane < 8) ? expf(b - m) : 0.0f);
#pragma unroll
    for (int o = 16; o; o >>= 1) s += __shfl_xor_sync(0xffffffffu, s, o);
    float lse = m + logf(s);
    float* q = out + (size_t)node * DOUTF;
    q[lane] = a - lse;
    if (lane < 8) q[32 + lane] = b - lse;
}

// ---------------- tiled fp32 GEMM with fused bias (+ optional BN + ReLU, + optional dual store) ----
__global__ __launch_bounds__(256) void k_gemm_fused(
    const float* __restrict__ A, const float* __restrict__ B, float* __restrict__ C,
    float* __restrict__ C2,
    int M, int K, int Nc,
    const float* __restrict__ bias,
    const float* __restrict__ gamma, const float* __restrict__ beta,
    const float* __restrict__ mean, const float* __restrict__ var,
    int bn_relu) {
    constexpr int BM = 128, BN = 64, BK = 16;
    __shared__ float As[BK][BM];
    __shared__ float Bs[BK][BN];

    int tid = threadIdx.x;
    int tx = tid & 15;
    int ty = tid >> 4;
    int row0 = blockIdx.y * BM;
    int col0 = blockIdx.x * BN;

    float acc[8][4];
#pragma unroll
    for (int i = 0; i < 8; i++)
#pragma unroll
        for (int j = 0; j < 4; j++) acc[i][j] = 0.0f;

    for (int k0 = 0; k0 < K; k0 += BK) {
#pragma unroll
        for (int l = 0; l < 2; l++) {
            int f4 = tid + l * 256;
            int ar = f4 >> 2;
            int ac = (f4 & 3) * 4;
            float4 av = make_float4(0.f, 0.f, 0.f, 0.f);
            int gr = row0 + ar;
            if (gr < M) av = *(const float4*)&A[(size_t)gr * K + k0 + ac];
            As[ac + 0][ar] = av.x;
            As[ac + 1][ar] = av.y;
            As[ac + 2][ar] = av.z;
            As[ac + 3][ar] = av.w;
        }
        {
            int br = tid >> 4;
            int bc = (tid & 15) * 4;
            float4 bv = make_float4(0.f, 0.f, 0.f, 0.f);
            int gc = col0 + bc;
            if (gc < Nc) bv = *(const float4*)&B[(size_t)(k0 + br) * Nc + gc];
            Bs[br][bc + 0] = bv.x;
            Bs[br][bc + 1] = bv.y;
            Bs[br][bc + 2] = bv.z;
            Bs[br][bc + 3] = bv.w;
        }
        __syncthreads();

#pragma unroll
        for (int k = 0; k < BK; k++) {
            float4 a0 = *(const float4*)&As[k][ty * 8];
            float4 a1 = *(const float4*)&As[k][ty * 8 + 4];
            float4 b0 = *(const float4*)&Bs[k][tx * 4];
            float ar[8] = {a0.x, a0.y, a0.z, a0.w, a1.x, a1.y, a1.z, a1.w};
            float br[4] = {b0.x, b0.y, b0.z, b0.w};
#pragma unroll
            for (int i = 0; i < 8; i++)
#pragma unroll
                for (int j = 0; j < 4; j++) acc[i][j] = fmaf(ar[i], br[j], acc[i][j]);
        }
        __syncthreads();
    }

#pragma unroll
    for (int j = 0; j < 4; j++) {
        int c = col0 + tx * 4 + j;
        if (c >= Nc) continue;
        float bb = bias ? bias[c] : 0.0f;
        float sc = 1.0f, sh = 0.0f;
        if (bn_relu) {
            sc = rsqrtf(var[c] + EPSV) * gamma[c];
            sh = beta[c] - mean[c] * sc;
        }
#pragma unroll
        for (int i = 0; i < 8; i++) {
            int r = row0 + ty * 8 + i;
            if (r >= M) continue;
            float v = acc[i][j] + bb;
            if (bn_relu) v = fmaxf(0.0f, fmaf(v, sc, sh));
            C[(size_t)r * Nc + c] = v;
            if (C2) C2[(size_t)r * Nc + c] = v;
        }
    }
}

// ---------------- launch ----------------
static inline int cdiv(long long a, long long b) { return (int)((a + b - 1) / b); }

extern "C" void kernel_launch(void* const* d_in, const int* in_sizes, int n_in,
                              void* d_out, int out_size) {
    const float* x = (const float*)d_in[0];
    const int* ei = (const int*)d_in[1];      // int32 (JAX default disables x64)
    const float* W1 = (const float*)d_in[2];
    const float* b1 = (const float*)d_in[3];
    const float* g1 = (const float*)d_in[4];
    const float* be1 = (const float*)d_in[5];
    const float* m1 = (const float*)d_in[6];
    const float* v1 = (const float*)d_in[7];
    const float* W2 = (const float*)d_in[8];
    const float* b2 = (const float*)d_in[9];
    const float* g2 = (const float*)d_in[10];
    const float* be2 = (const float*)d_in[11];
    const float* m2 = (const float*)d_in[12];
    const float* v2 = (const float*)d_in[13];
    const float* W3 = (const float*)d_in[14];
    const float* b3 = (const float*)d_in[15];
    const int E = in_sizes[1] / 2;
    const int* src = ei;
    const int* dst = ei + E;

    float* out = (float*)d_out;                       // NN x 40 region
    const bool have_emb = out_size >= NN * (DOUTF + DH);
    float* emb = out + (size_t)NN * DOUTF;            // NN x 256 region (if present)

    float *dinv, *selfn, *zbuf, *h, *z3, *csr_w;
    int *cnt, *cur, *off, *blk, *csr_src;
    cudaGetSymbolAddress((void**)&dinv, g_dinv);
    cudaGetSymbolAddress((void**)&selfn, g_selfn);
    cudaGetSymbolAddress((void**)&zbuf, g_z);
    cudaGetSymbolAddress((void**)&h, g_h);
    cudaGetSymbolAddress((void**)&z3, g_z3);
    cudaGetSymbolAddress((void**)&cnt, g_cnt);
    cudaGetSymbolAddress((void**)&cur, g_cur);
    cudaGetSymbolAddress((void**)&off, g_off);
    cudaGetSymbolAddress((void**)&blk, g_blk);
    cudaGetSymbolAddress((void**)&csr_src, g_csr_src);
    cudaGetSymbolAddress((void**)&csr_w, g_csr_w);

    const int T = 256;

    // ---- CSR build ----
    k_zero_int<<<cdiv(NN, T), T>>>(cnt, NN);
    k_count_int<<<cdiv(E, T), T>>>(dst, E, cnt);
    k_norms_from_cnt<<<cdiv(NN, T), T>>>(cnt, dinv, selfn, NN);
    k_scan_block<<<NB_SCAN, 1024>>>(cnt, off, blk, NN);
    k_scan_top<<<1, 32>>>(blk, NB_SCAN);
    k_scan_add<<<cdiv(NN, T), T>>>(off, blk, NN, E);
    k_zero_int<<<cdiv(NN, T), T>>>(cur, NN);
    k_fill<<<cdiv(E, T), T>>>(src, dst, E, off, cur, dinv, csr_src, csr_w);

    // ---- layer 1: z1 = Agg(x) [N,128]; h1 = relu(bn1(z1 @ W1 + b1)) ----
    k_gather<DIN><<<NN, DIN>>>(x, zbuf, off, csr_src, csr_w, dinv, selfn);
    {
        dim3 grid((DH + 63) / 64, (NN + 127) / 128);
        k_gemm_fused<<<grid, 256>>>(zbuf, W1, h, nullptr, NN, DIN, DH, b1, g1, be1, m1, v1, 1);
    }

    // ---- layer 2: z2 = Agg(h1) [N,256]; h2 = relu(bn2(z2 @ W2 + b2)) ----
    k_gather<DH><<<NN, DH>>>(h, zbuf, off, csr_src, csr_w, dinv, selfn);
    {
        dim3 grid((DH + 63) / 64, (NN + 127) / 128);
        k_gemm_fused<<<grid, 256>>>(zbuf, W2, h, have_emb ? emb : nullptr,
                                    NN, DH, DH, b2, g2, be2, m2, v2, 1);
    }

    // ---- layer 3: z3 = h2 @ W3 [N,40]; out = log_softmax(Agg(z3) + b3) ----
    {
        dim3 grid((DOUTF + 63) / 64, (NN + 127) / 128);
        k_gemm_fused<<<grid, 256>>>(h, W3, z3, nullptr, NN, DH, DOUTF,
                                    nullptr, nullptr, nullptr, nullptr, nullptr, 0);
    }
    k_gather40_softmax<<<cdiv(NN, 8), 256>>>(z3, b3, out, off, csr_src, csr_w, dinv, selfn);
}

// round 7
// speedup vs baseline: 2.3929x; 1.8675x over previous
#include <cuda_runtime.h>
#include <math.h>
#include <stdint.h>

#define NN 169343
#define DIN 128
#define DH 256
#define DOUTF 40
#define EPSV 1e-5f
#define EMAX 2500000
#define NB_SCAN ((NN + 1023) / 1024)

// ---------------- scratch (static device globals) ----------------
__device__ __align__(128) float g_dinv[NN];
__device__ __align__(128) float g_selfn[NN];
__device__ __align__(128) int   g_cnt[NN];
__device__ __align__(128) int   g_cur[NN];
__device__ __align__(128) int   g_off[NN + 1];
__device__ __align__(128) int   g_blk[256];
__device__ __align__(128) int   g_csr_src[EMAX];
__device__ __align__(128) float g_csr_w[EMAX];
__device__ __align__(128) float g_z[(size_t)NN * DH];
__device__ __align__(128) float g_h[(size_t)NN * DH];
__device__ __align__(128) float g_z3[(size_t)NN * DOUTF];

// ---------------- CSR construction ----------------
__global__ void k_zero_int(int* __restrict__ p, int n) {
    int i = blockIdx.x * blockDim.x + threadIdx.x;
    if (i < n) p[i] = 0;
}

__global__ void k_count_int(const int* __restrict__ dst, int E, int* __restrict__ cnt) {
    int e = blockIdx.x * blockDim.x + threadIdx.x;
    if (e < E) atomicAdd(&cnt[dst[e]], 1);
}

__global__ void k_norms_from_cnt(const int* __restrict__ cnt, float* __restrict__ dinv,
                                 float* __restrict__ selfn, int n) {
    int i = blockIdx.x * blockDim.x + threadIdx.x;
    if (i < n) {
        float deg = (float)cnt[i] + 1.0f;
        dinv[i] = rsqrtf(deg);
        selfn[i] = 1.0f / deg;
    }
}

__global__ __launch_bounds__(1024) void k_scan_block(const int* __restrict__ cnt,
                                                     int* __restrict__ off,
                                                     int* __restrict__ blk, int n) {
    __shared__ int s[1024];
    int t = threadIdx.x;
    int i = blockIdx.x * 1024 + t;
    int v = (i < n) ? cnt[i] : 0;
    s[t] = v;
    __syncthreads();
#pragma unroll
    for (int o = 1; o < 1024; o <<= 1) {
        int add = (t >= o) ? s[t - o] : 0;
        __syncthreads();
        s[t] += add;
        __syncthreads();
    }
    if (i <= n) off[i] = s[t] - v;
    if (t == 1023) blk[blockIdx.x] = s[1023];
}

__global__ void k_scan_top(int* __restrict__ blk, int nb) {
    if (threadIdx.x == 0 && blockIdx.x == 0) {
        int run = 0;
        for (int b = 0; b < nb; b++) { int v = blk[b]; blk[b] = run; run += v; }
    }
}

__global__ void k_scan_add(int* __restrict__ off, const int* __restrict__ blk, int n, int E) {
    int i = blockIdx.x * blockDim.x + threadIdx.x;
    if (i < n) off[i] += blk[i / 1024];
    if (i == 0) off[n] = E;
}

__global__ void k_fill(const int* __restrict__ src, const int* __restrict__ dst, int E,
                       const int* __restrict__ off, int* __restrict__ cur,
                       const float* __restrict__ dinv,
                       int* __restrict__ csr_src, float* __restrict__ csr_w) {
    int e = blockIdx.x * blockDim.x + threadIdx.x;
    if (e >= E) return;
    int d = dst[e];
    int s = src[e];
    int pos = off[d] + atomicAdd(&cur[d], 1);
    csr_src[pos] = s;
    csr_w[pos] = dinv[s];
}

// ---------------- CSR gather ----------------
template <int F>
__global__ __launch_bounds__(F) void k_gather(const float* __restrict__ feat,
                                              float* __restrict__ aggout,
                                              const int* __restrict__ off,
                                              const int* __restrict__ csr_src,
                                              const float* __restrict__ csr_w,
                                              const float* __restrict__ dinv,
                                              const float* __restrict__ selfn) {
    int node = blockIdx.x;
    int t = threadIdx.x;
    int beg = off[node], end = off[node + 1];
    float a0 = 0.f, a1 = 0.f, a2 = 0.f, a3 = 0.f;
    int e = beg;
    for (; e + 3 < end; e += 4) {
        int s0 = csr_src[e], s1 = csr_src[e + 1], s2 = csr_src[e + 2], s3 = csr_src[e + 3];
        float w0 = csr_w[e], w1 = csr_w[e + 1], w2 = csr_w[e + 2], w3 = csr_w[e + 3];
        a0 = fmaf(w0, __ldg(feat + (size_t)s0 * F + t), a0);
        a1 = fmaf(w1, __ldg(feat + (size_t)s1 * F + t), a1);
        a2 = fmaf(w2, __ldg(feat + (size_t)s2 * F + t), a2);
        a3 = fmaf(w3, __ldg(feat + (size_t)s3 * F + t), a3);
    }
    for (; e < end; e++)
        a0 = fmaf(csr_w[e], __ldg(feat + (size_t)csr_src[e] * F + t), a0);
    float acc = (a0 + a1) + (a2 + a3);
    float self = feat[(size_t)node * F + t];
    aggout[(size_t)node * F + t] = fmaf(dinv[node], acc, selfn[node] * self);
}

// ---------------- fused layer-3 gather (+bias) + log_softmax ----------------
__global__ __launch_bounds__(256) void k_gather40_softmax(
    const float* __restrict__ z3, const float* __restrict__ b3,
    float* __restrict__ out,
    const int* __restrict__ off, const int* __restrict__ csr_src,
    const float* __restrict__ csr_w,
    const float* __restrict__ dinv, const float* __restrict__ selfn) {
    int node = blockIdx.x * 8 + (threadIdx.x >> 5);
    int lane = threadIdx.x & 31;
    if (node >= NN) return;
    int beg = off[node], end = off[node + 1];
    float aa = 0.f, ab = 0.f;
    for (int e = beg; e < end; e++) {
        int s = csr_src[e];
        float w = csr_w[e];
        const float* fs = z3 + (size_t)s * DOUTF;
        aa = fmaf(w, fs[lane], aa);
        if (lane < 8) ab = fmaf(w, fs[32 + lane], ab);
    }
    float di = dinv[node], sn = selfn[node];
    const float* fz = z3 + (size_t)node * DOUTF;
    float a = fmaf(di, aa, fmaf(sn, fz[lane], b3[lane]));
    float b = (lane < 8) ? fmaf(di, ab, fmaf(sn, fz[32 + lane], b3[32 + lane])) : -3.402823e38f;
    float m = fmaxf(a, b);
#pragma unroll
    for (int o = 16; o; o >>= 1) m = fmaxf(m, __shfl_xor_sync(0xffffffffu, m, o));
    float s = expf(a - m) + ((lane < 8) ? expf(b - m) : 0.0f);
#pragma unroll
    for (int o = 16; o; o >>= 1) s += __shfl_xor_sync(0xffffffffu, s, o);
    float lse = m + logf(s);
    float* q = out + (size_t)node * DOUTF;
    q[lane] = a - lse;
    if (lane < 8) q[32 + lane] = b - lse;
}

// ---------------- split-bf16 helpers ----------------
__device__ __forceinline__ float trunc_bf16(float x) {
    return __uint_as_float(__float_as_uint(x) & 0xFFFF0000u);
}
// pack high-16 bits of x (low half) and y (high half): bf16x2 {x, y}
__device__ __forceinline__ uint32_t pack_hi(float x, float y) {
    uint32_t r;
    asm("prmt.b32 %0, %1, %2, 0x7632;" : "=r"(r)
        : "r"(__float_as_uint(x)), "r"(__float_as_uint(y)));
    return r;
}
__device__ __forceinline__ void mma_bf16(float* c, const uint32_t* a, uint32_t b0, uint32_t b1) {
    asm volatile(
        "mma.sync.aligned.m16n8k16.row.col.f32.bf16.bf16.f32 "
        "{%0,%1,%2,%3}, {%4,%5,%6,%7}, {%8,%9}, {%0,%1,%2,%3};"
        : "+f"(c[0]), "+f"(c[1]), "+f"(c[2]), "+f"(c[3])
        : "r"(a[0]), "r"(a[1]), "r"(a[2]), "r"(a[3]), "r"(b0), "r"(b1));
}

// ---------------- tensor-core GEMM (split-bf16 x3) with fused bias/BN/ReLU epilogue ----------
// C[M,Nc] = A[M,K] @ B[K,Nc]; BM=128, BN=64, BK=32; 8 warps, warp tile 32x32
__global__ __launch_bounds__(256) void k_gemm_tc(
    const float* __restrict__ A, const float* __restrict__ B,
    float* __restrict__ C, float* __restrict__ C2,
    int M, int K, int Nc,
    const float* __restrict__ bias,
    const float* __restrict__ gamma, const float* __restrict__ beta,
    const float* __restrict__ mean, const float* __restrict__ var,
    int bn_relu) {
    constexpr int BM = 128, BN = 64, BK = 32;
    constexpr int SP = 20;  // smem pair-stride (conflict-free: 20*b+a distinct mod 32)
    __shared__ uint32_t As_h[BM][SP], As_l[BM][SP];
    __shared__ uint32_t Bs_h[BN][SP], Bs_l[BN][SP];

    int tid = threadIdx.x;
    int lane = tid & 31;
    int wid = tid >> 5;
    int wm = (wid & 3) * 32;     // warp M origin within block
    int wn = (wid >> 2) * 32;    // warp N origin within block
    int row0 = blockIdx.y * BM;
    int col0 = blockIdx.x * BN;
    int g = lane >> 2;           // groupID
    int tg = lane & 3;           // threadID_in_group

    float c[2][4][4];
#pragma unroll
    for (int mi = 0; mi < 2; mi++)
#pragma unroll
        for (int ni = 0; ni < 4; ni++)
#pragma unroll
            for (int r = 0; r < 4; r++) c[mi][ni][r] = 0.0f;

    for (int k0 = 0; k0 < K; k0 += BK) {
        // ---- A tile: 128x32 floats -> split bf16 pairs ----
#pragma unroll
        for (int l = 0; l < 4; l++) {
            int idx = tid + l * 256;   // 0..1023
            int m = idx >> 3;
            int cg = idx & 7;          // float4 group within row
            int gr = row0 + m;
            float4 v = make_float4(0.f, 0.f, 0.f, 0.f);
            if (gr < M) v = *(const float4*)&A[(size_t)gr * K + k0 + cg * 4];
            int kp = cg * 2;
            As_h[m][kp]     = pack_hi(v.x, v.y);
            As_l[m][kp]     = pack_hi(v.x - trunc_bf16(v.x), v.y - trunc_bf16(v.y));
            As_h[m][kp + 1] = pack_hi(v.z, v.w);
            As_l[m][kp + 1] = pack_hi(v.z - trunc_bf16(v.z), v.w - trunc_bf16(v.w));
        }
        // ---- B tile: 32x64 floats -> transposed split bf16 pairs Bs[n][kp] ----
        {
            int kp = tid >> 4;         // 0..15
            int cg = tid & 15;         // 0..15 -> cols 4*cg
            int gk = k0 + kp * 2;
            int gc = col0 + cg * 4;
            float4 u = make_float4(0.f, 0.f, 0.f, 0.f);
            float4 w = make_float4(0.f, 0.f, 0.f, 0.f);
            if (gc < Nc) {
                u = *(const float4*)&B[(size_t)gk * Nc + gc];
                w = *(const float4*)&B[(size_t)(gk + 1) * Nc + gc];
            }
            int n = cg * 4;
            Bs_h[n + 0][kp] = pack_hi(u.x, w.x);
            Bs_l[n + 0][kp] = pack_hi(u.x - trunc_bf16(u.x), w.x - trunc_bf16(w.x));
            Bs_h[n + 1][kp] = pack_hi(u.y, w.y);
            Bs_l[n + 1][kp] = pack_hi(u.y - trunc_bf16(u.y), w.y - trunc_bf16(w.y));
            Bs_h[n + 2][kp] = pack_hi(u.z, w.z);
            Bs_l[n + 2][kp] = pack_hi(u.z - trunc_bf16(u.z), w.z - trunc_bf16(w.z));
            Bs_h[n + 3][kp] = pack_hi(u.w, w.w);
            Bs_l[n + 3][kp] = pack_hi(u.w - trunc_bf16(u.w), w.w - trunc_bf16(w.w));
        }
        __syncthreads();

#pragma unroll
        for (int ks = 0; ks < 2; ks++) {
            int kp0 = ks * 8;
            uint32_t ah[2][4], al[2][4];
#pragma unroll
            for (int mi = 0; mi < 2; mi++) {
                int r = wm + mi * 16 + g;
                int cA = kp0 + tg;
                ah[mi][0] = As_h[r][cA];     al[mi][0] = As_l[r][cA];
                ah[mi][1] = As_h[r + 8][cA]; al[mi][1] = As_l[r + 8][cA];
                ah[mi][2] = As_h[r][cA + 4]; al[mi][2] = As_l[r][cA + 4];
                ah[mi][3] = As_h[r + 8][cA + 4]; al[mi][3] = As_l[r + 8][cA + 4];
            }
#pragma unroll
            for (int ni = 0; ni < 4; ni++) {
                int n = wn + ni * 8 + g;
                int cB = kp0 + tg;
                uint32_t bh0 = Bs_h[n][cB], bh1 = Bs_h[n][cB + 4];
                uint32_t bl0 = Bs_l[n][cB], bl1 = Bs_l[n][cB + 4];
#pragma unroll
                for (int mi = 0; mi < 2; mi++) {
                    mma_bf16(c[mi][ni], ah[mi], bh0, bh1);
                    mma_bf16(c[mi][ni], al[mi], bh0, bh1);
                    mma_bf16(c[mi][ni], ah[mi], bl0, bl1);
                }
            }
        }
        __syncthreads();
    }

    // ---- epilogue ----
#pragma unroll
    for (int ni = 0; ni < 4; ni++) {
        int cc = col0 + wn + ni * 8 + 2 * tg;
        if (cc >= Nc) continue;
        float bb0 = bias ? bias[cc] : 0.0f;
        float bb1 = bias ? bias[cc + 1] : 0.0f;
        float sc0 = 1.0f, sh0 = 0.0f, sc1 = 1.0f, sh1 = 0.0f;
        if (bn_relu) {
            sc0 = rsqrtf(var[cc] + EPSV) * gamma[cc];
            sh0 = beta[cc] - mean[cc] * sc0;
            sc1 = rsqrtf(var[cc + 1] + EPSV) * gamma[cc + 1];
            sh1 = beta[cc + 1] - mean[cc + 1] * sc1;
        }
#pragma unroll
        for (int mi = 0; mi < 2; mi++) {
#pragma unroll
            for (int half = 0; half < 2; half++) {
                int r = row0 + wm + mi * 16 + g + half * 8;
                if (r >= M) continue;
                float v0 = c[mi][ni][half * 2 + 0] + bb0;
                float v1 = c[mi][ni][half * 2 + 1] + bb1;
                if (bn_relu) {
                    v0 = fmaxf(0.0f, fmaf(v0, sc0, sh0));
                    v1 = fmaxf(0.0f, fmaf(v1, sc1, sh1));
                }
                float2 vv = make_float2(v0, v1);
                *(float2*)&C[(size_t)r * Nc + cc] = vv;
                if (C2) *(float2*)&C2[(size_t)r * Nc + cc] = vv;
            }
        }
    }
}

// ---------------- launch ----------------
static inline int cdiv(long long a, long long b) { return (int)((a + b - 1) / b); }

extern "C" void kernel_launch(void* const* d_in, const int* in_sizes, int n_in,
                              void* d_out, int out_size) {
    const float* x = (const float*)d_in[0];
    const int* ei = (const int*)d_in[1];
    const float* W1 = (const float*)d_in[2];
    const float* b1 = (const float*)d_in[3];
    const float* g1 = (const float*)d_in[4];
    const float* be1 = (const float*)d_in[5];
    const float* m1 = (const float*)d_in[6];
    const float* v1 = (const float*)d_in[7];
    const float* W2 = (const float*)d_in[8];
    const float* b2 = (const float*)d_in[9];
    const float* g2 = (const float*)d_in[10];
    const float* be2 = (const float*)d_in[11];
    const float* m2 = (const float*)d_in[12];
    const float* v2 = (const float*)d_in[13];
    const float* W3 = (const float*)d_in[14];
    const float* b3 = (const float*)d_in[15];
    const int E = in_sizes[1] / 2;
    const int* src = ei;
    const int* dst = ei + E;

    float* out = (float*)d_out;
    const bool have_emb = out_size >= NN * (DOUTF + DH);
    float* emb = out + (size_t)NN * DOUTF;

    float *dinv, *selfn, *zbuf, *h, *z3, *csr_w;
    int *cnt, *cur, *off, *blk, *csr_src;
    cudaGetSymbolAddress((void**)&dinv, g_dinv);
    cudaGetSymbolAddress((void**)&selfn, g_selfn);
    cudaGetSymbolAddress((void**)&zbuf, g_z);
    cudaGetSymbolAddress((void**)&h, g_h);
    cudaGetSymbolAddress((void**)&z3, g_z3);
    cudaGetSymbolAddress((void**)&cnt, g_cnt);
    cudaGetSymbolAddress((void**)&cur, g_cur);
    cudaGetSymbolAddress((void**)&off, g_off);
    cudaGetSymbolAddress((void**)&blk, g_blk);
    cudaGetSymbolAddress((void**)&csr_src, g_csr_src);
    cudaGetSymbolAddress((void**)&csr_w, g_csr_w);

    const int T = 256;

    // ---- CSR build ----
    k_zero_int<<<cdiv(NN, T), T>>>(cnt, NN);
    k_count_int<<<cdiv(E, T), T>>>(dst, E, cnt);
    k_norms_from_cnt<<<cdiv(NN, T), T>>>(cnt, dinv, selfn, NN);
    k_scan_block<<<NB_SCAN, 1024>>>(cnt, off, blk, NN);
    k_scan_top<<<1, 32>>>(blk, NB_SCAN);
    k_scan_add<<<cdiv(NN, T), T>>>(off, blk, NN, E);
    k_zero_int<<<cdiv(NN, T), T>>>(cur, NN);
    k_fill<<<cdiv(E, T), T>>>(src, dst, E, off, cur, dinv, csr_src, csr_w);

    dim3 gridH((DH + 63) / 64, (NN + 127) / 128);
    dim3 gridO((DOUTF + 63) / 64, (NN + 127) / 128);

    // ---- layer 1 ----
    k_gather<DIN><<<NN, DIN>>>(x, zbuf, off, csr_src, csr_w, dinv, selfn);
    k_gemm_tc<<<gridH, 256>>>(zbuf, W1, h, nullptr, NN, DIN, DH, b1, g1, be1, m1, v1, 1);

    // ---- layer 2 ----
    k_gather<DH><<<NN, DH>>>(h, zbuf, off, csr_src, csr_w, dinv, selfn);
    k_gemm_tc<<<gridH, 256>>>(zbuf, W2, h, have_emb ? emb : nullptr,
                              NN, DH, DH, b2, g2, be2, m2, v2, 1);

    // ---- layer 3 ----
    k_gemm_tc<<<gridO, 256>>>(h, W3, z3, nullptr, NN, DH, DOUTF,
                              nullptr, nullptr, nullptr, nullptr, nullptr, 0);
    k_gather40_softmax<<<cdiv(NN, 8), 256>>>(z3, b3, out, off, csr_src, csr_w, dinv, selfn);
}

// round 9
// speedup vs baseline: 3.7894x; 1.5836x over previous
#include <cuda_runtime.h>
#include <cuda_fp16.h>
#include <math.h>
#include <stdint.h>

#define NN 169343
#define DIN 128
#define DH 256
#define DOUTF 40
#define EPSV 1e-5f
#define EMAX 2500000
#define NB_SCAN ((NN + 1023) / 1024)

// ---------------- scratch (static device globals) ----------------
__device__ __align__(128) float  g_dinv[NN];
__device__ __align__(128) float  g_selfn[NN];
__device__ __align__(128) int    g_cnt[NN];
__device__ __align__(128) int    g_cur[NN];
__device__ __align__(128) int    g_off[NN + 1];
__device__ __align__(128) int    g_blk[256];
__device__ __align__(128) int    g_csr_src[EMAX];
__device__ __align__(128) float  g_csr_w[EMAX];
__device__ __align__(128) __half g_fa[(size_t)NN * DH];   // feature table (x / h1 / h2)
__device__ __align__(128) __half g_fz[(size_t)NN * DH];   // aggregated table (z1 / z2)
__device__ __align__(128) float  g_z3[(size_t)NN * DOUTF];
// pre-split, pre-transposed, pre-paired weights: [Nc][K/2] u32 = {fp16(k), fp16(k+1)}
__device__ __align__(128) uint32_t g_w1h[DH * (DIN / 2)], g_w1l[DH * (DIN / 2)];
__device__ __align__(128) uint32_t g_w2h[DH * (DH / 2)],  g_w2l[DH * (DH / 2)];
__device__ __align__(128) uint32_t g_w3h[DOUTF * (DH / 2)], g_w3l[DOUTF * (DH / 2)];

// ---------------- CSR construction ----------------
__global__ void k_zero_int(int* __restrict__ p, int n) {
    int i = blockIdx.x * blockDim.x + threadIdx.x;
    if (i < n) p[i] = 0;
}
__global__ void k_count_int(const int* __restrict__ dst, int E, int* __restrict__ cnt) {
    int e = blockIdx.x * blockDim.x + threadIdx.x;
    if (e < E) atomicAdd(&cnt[dst[e]], 1);
}
__global__ void k_norms_from_cnt(const int* __restrict__ cnt, float* __restrict__ dinv,
                                 float* __restrict__ selfn, int n) {
    int i = blockIdx.x * blockDim.x + threadIdx.x;
    if (i < n) {
        float deg = (float)cnt[i] + 1.0f;
        dinv[i] = rsqrtf(deg);
        selfn[i] = 1.0f / deg;
    }
}
__global__ __launch_bounds__(1024) void k_scan_block(const int* __restrict__ cnt,
                                                     int* __restrict__ off,
                                                     int* __restrict__ blk, int n) {
    __shared__ int s[1024];
    int t = threadIdx.x;
    int i = blockIdx.x * 1024 + t;
    int v = (i < n) ? cnt[i] : 0;
    s[t] = v;
    __syncthreads();
#pragma unroll
    for (int o = 1; o < 1024; o <<= 1) {
        int add = (t >= o) ? s[t - o] : 0;
        __syncthreads();
        s[t] += add;
        __syncthreads();
    }
    if (i <= n) off[i] = s[t] - v;
    if (t == 1023) blk[blockIdx.x] = s[1023];
}
__global__ void k_scan_top(int* __restrict__ blk, int nb) {
    if (threadIdx.x == 0 && blockIdx.x == 0) {
        int run = 0;
        for (int b = 0; b < nb; b++) { int v = blk[b]; blk[b] = run; run += v; }
    }
}
__global__ void k_scan_add(int* __restrict__ off, const int* __restrict__ blk, int n, int E) {
    int i = blockIdx.x * blockDim.x + threadIdx.x;
    if (i < n) off[i] += blk[i / 1024];
    if (i == 0) off[n] = E;
}
__global__ void k_fill(const int* __restrict__ src, const int* __restrict__ dst, int E,
                       const int* __restrict__ off, int* __restrict__ cur,
                       const float* __restrict__ dinv,
                       int* __restrict__ csr_src, float* __restrict__ csr_w) {
    int e = blockIdx.x * blockDim.x + threadIdx.x;
    if (e >= E) return;
    int d = dst[e];
    int s = src[e];
    int pos = off[d] + atomicAdd(&cur[d], 1);
    csr_src[pos] = s;
    csr_w[pos] = dinv[s];
}

// ---------------- fp32 -> fp16 convert (x table) ----------------
__global__ void k_f32_to_f16(const float2* __restrict__ in, __half2* __restrict__ out, int n2) {
    int i = blockIdx.x * blockDim.x + threadIdx.x;
    if (i < n2) {
        float2 v = in[i];
        out[i] = __floats2half2_rn(v.x, v.y);
    }
}

// ---------------- weight split: W[K][Nc] fp32 -> Wp_h/Wp_l [Nc][K/2] u32 (paired fp16) ----------
__global__ void k_split_w(const float* __restrict__ W, uint32_t* __restrict__ Wh,
                          uint32_t* __restrict__ Wl, int K, int Nc) {
    int idx = blockIdx.x * blockDim.x + threadIdx.x;
    int Kp = K / 2;
    if (idx >= Nc * Kp) return;
    int n = idx / Kp;
    int kp = idx - n * Kp;
    float w0 = W[(size_t)(2 * kp) * Nc + n];
    float w1 = W[(size_t)(2 * kp + 1) * Nc + n];
    __half h0 = __float2half_rn(w0), h1 = __float2half_rn(w1);
    __half l0 = __float2half_rn(w0 - __half2float(h0));
    __half l1 = __float2half_rn(w1 - __half2float(h1));
    __half2 H = __halves2half2(h0, h1), L = __halves2half2(l0, l1);
    Wh[idx] = *(uint32_t*)&H;
    Wl[idx] = *(uint32_t*)&L;
}

// ---------------- CSR gather (fp16 in/out, fp32 accum): half2 lanes ----------------
template <int F>
__global__ __launch_bounds__(F / 2) void k_gather_h2(const __half* __restrict__ feat,
                                                     __half* __restrict__ aggout,
                                                     const int* __restrict__ off,
                                                     const int* __restrict__ csr_src,
                                                     const float* __restrict__ csr_w,
                                                     const float* __restrict__ dinv,
                                                     const float* __restrict__ selfn) {
    int node = blockIdx.x;
    int t = threadIdx.x;  // half2 lane: features 2t, 2t+1
    int beg = off[node], end = off[node + 1];
    float ax0 = 0.f, ay0 = 0.f, ax1 = 0.f, ay1 = 0.f, ax2 = 0.f, ay2 = 0.f, ax3 = 0.f, ay3 = 0.f;
    int e = beg;
    for (; e + 3 < end; e += 4) {
        int s0 = csr_src[e], s1 = csr_src[e + 1], s2 = csr_src[e + 2], s3 = csr_src[e + 3];
        float w0 = csr_w[e], w1 = csr_w[e + 1], w2 = csr_w[e + 2], w3 = csr_w[e + 3];
        float2 v0 = __half22float2(*(const __half2*)(feat + (size_t)s0 * F + 2 * t));
        float2 v1 = __half22float2(*(const __half2*)(feat + (size_t)s1 * F + 2 * t));
        float2 v2 = __half22float2(*(const __half2*)(feat + (size_t)s2 * F + 2 * t));
        float2 v3 = __half22float2(*(const __half2*)(feat + (size_t)s3 * F + 2 * t));
        ax0 = fmaf(w0, v0.x, ax0); ay0 = fmaf(w0, v0.y, ay0);
        ax1 = fmaf(w1, v1.x, ax1); ay1 = fmaf(w1, v1.y, ay1);
        ax2 = fmaf(w2, v2.x, ax2); ay2 = fmaf(w2, v2.y, ay2);
        ax3 = fmaf(w3, v3.x, ax3); ay3 = fmaf(w3, v3.y, ay3);
    }
    for (; e < end; e++) {
        float w = csr_w[e];
        float2 v = __half22float2(*(const __half2*)(feat + (size_t)csr_src[e] * F + 2 * t));
        ax0 = fmaf(w, v.x, ax0); ay0 = fmaf(w, v.y, ay0);
    }
    float ax = (ax0 + ax1) + (ax2 + ax3);
    float ay = (ay0 + ay1) + (ay2 + ay3);
    float2 self = __half22float2(*(const __half2*)(feat + (size_t)node * F + 2 * t));
    float di = dinv[node], sn = selfn[node];
    __half2 r = __floats2half2_rn(fmaf(di, ax, sn * self.x), fmaf(di, ay, sn * self.y));
    *(__half2*)(aggout + (size_t)node * F + 2 * t) = r;
}

// ---------------- fused layer-3 gather (+bias) + log_softmax ----------------
__global__ __launch_bounds__(256) void k_gather40_softmax(
    const float* __restrict__ z3, const float* __restrict__ b3,
    float* __restrict__ out,
    const int* __restrict__ off, const int* __restrict__ csr_src,
    const float* __restrict__ csr_w,
    const float* __restrict__ dinv, const float* __restrict__ selfn) {
    int node = blockIdx.x * 8 + (threadIdx.x >> 5);
    int lane = threadIdx.x & 31;
    if (node >= NN) return;
    int beg = off[node], end = off[node + 1];
    float aa = 0.f, ab = 0.f;
    for (int e = beg; e < end; e++) {
        int s = csr_src[e];
        float w = csr_w[e];
        const float* fs = z3 + (size_t)s * DOUTF;
        aa = fmaf(w, fs[lane], aa);
        if (lane < 8) ab = fmaf(w, fs[32 + lane], ab);
    }
    float di = dinv[node], sn = selfn[node];
    const float* fz = z3 + (size_t)node * DOUTF;
    float a = fmaf(di, aa, fmaf(sn, fz[lane], b3[lane]));
    float b = (lane < 8) ? fmaf(di, ab, fmaf(sn, fz[32 + lane], b3[32 + lane])) : -3.402823e38f;
    float m = fmaxf(a, b);
#pragma unroll
    for (int o = 16; o; o >>= 1) m = fmaxf(m, __shfl_xor_sync(0xffffffffu, m, o));
    float s = expf(a - m) + ((lane < 8) ? expf(b - m) : 0.0f);
#pragma unroll
    for (int o = 16; o; o >>= 1) s += __shfl_xor_sync(0xffffffffu, s, o);
    float lse = m + logf(s);
    float* q = out + (size_t)node * DOUTF;
    q[lane] = a - lse;
    if (lane < 8) q[32 + lane] = b - lse;
}

// ---------------- fp16 MMA ----------------
__device__ __forceinline__ void mma_f16(float* c, const uint32_t* a, uint32_t b0, uint32_t b1) {
    asm volatile(
        "mma.sync.aligned.m16n8k16.row.col.f32.f16.f16.f32 "
        "{%0,%1,%2,%3}, {%4,%5,%6,%7}, {%8,%9}, {%0,%1,%2,%3};"
        : "+f"(c[0]), "+f"(c[1]), "+f"(c[2]), "+f"(c[3])
        : "r"(a[0]), "r"(a[1]), "r"(a[2]), "r"(a[3]), "r"(b0), "r"(b1));
}

// ---------------- tensor-core GEMM: A fp16, W split fp16 (2 MMAs/k16) ----------------
// C = A[M,K] @ W[K,Nc]; outputs: fp32 (optional) and/or fp16 table (optional)
__global__ __launch_bounds__(256) void k_gemm_f16(
    const __half* __restrict__ A,
    const uint32_t* __restrict__ Bph, const uint32_t* __restrict__ Bpl,
    float* __restrict__ Cf32, __half* __restrict__ Cf16,
    int M, int K, int Nc,
    const float* __restrict__ bias,
    const float* __restrict__ gamma, const float* __restrict__ beta,
    const float* __restrict__ mean, const float* __restrict__ var,
    int bn_relu) {
    constexpr int BM = 128, BN = 64, BK = 32;
    constexpr int SP = 20;  // pair-stride w/ pad
    __shared__ uint32_t As[BM][SP];
    __shared__ uint32_t Bs_h[BN][SP], Bs_l[BN][SP];

    int tid = threadIdx.x;
    int lane = tid & 31;
    int wid = tid >> 5;
    int wm = (wid & 3) * 32;
    int wn = (wid >> 2) * 32;
    int row0 = blockIdx.y * BM;
    int col0 = blockIdx.x * BN;
    int g = lane >> 2;
    int tg = lane & 3;
    int Kp = K >> 1;

    float c[2][4][4];
#pragma unroll
    for (int mi = 0; mi < 2; mi++)
#pragma unroll
        for (int ni = 0; ni < 4; ni++)
#pragma unroll
            for (int r = 0; r < 4; r++) c[mi][ni][r] = 0.0f;

    for (int k0 = 0; k0 < K; k0 += BK) {
        // ---- A tile: 128 rows x 16 kpairs (u32) ; uint4 loads (4 kpairs each) ----
#pragma unroll
        for (int l = 0; l < 2; l++) {
            int idx = tid + l * 256;        // 0..511
            int m = idx >> 2;
            int q = idx & 3;                // uint4 within row
            int gr = row0 + m;
            uint4 v = make_uint4(0u, 0u, 0u, 0u);
            if (gr < M) v = *(const uint4*)(A + (size_t)gr * K + k0 + q * 8);
            As[m][q * 4 + 0] = v.x;
            As[m][q * 4 + 1] = v.y;
            As[m][q * 4 + 2] = v.z;
            As[m][q * 4 + 3] = v.w;
        }
        // ---- B tiles: [BN][16 kpairs] direct from pre-paired weights ----
#pragma unroll
        for (int l = 0; l < 4; l++) {
            int idx = tid + l * 256;        // 0..1023
            int n = idx >> 4;
            int kp = idx & 15;
            int gc = col0 + n;
            uint32_t vh = 0u, vl = 0u;
            if (gc < Nc) {
                size_t o = (size_t)gc * Kp + (k0 >> 1) + kp;
                vh = Bph[o];
                vl = Bpl[o];
            }
            Bs_h[n][kp] = vh;
            Bs_l[n][kp] = vl;
        }
        __syncthreads();

#pragma unroll
        for (int ks = 0; ks < 2; ks++) {
            int kp0 = ks * 8;
            uint32_t a[2][4];
#pragma unroll
            for (int mi = 0; mi < 2; mi++) {
                int r = wm + mi * 16 + g;
                int cA = kp0 + tg;
                a[mi][0] = As[r][cA];
                a[mi][1] = As[r + 8][cA];
                a[mi][2] = As[r][cA + 4];
                a[mi][3] = As[r + 8][cA + 4];
            }
#pragma unroll
            for (int ni = 0; ni < 4; ni++) {
                int n = wn + ni * 8 + g;
                int cB = kp0 + tg;
                uint32_t bh0 = Bs_h[n][cB], bh1 = Bs_h[n][cB + 4];
                uint32_t bl0 = Bs_l[n][cB], bl1 = Bs_l[n][cB + 4];
#pragma unroll
                for (int mi = 0; mi < 2; mi++) {
                    mma_f16(c[mi][ni], a[mi], bh0, bh1);
                    mma_f16(c[mi][ni], a[mi], bl0, bl1);
                }
            }
        }
        __syncthreads();
    }

    // ---- epilogue ----
#pragma unroll
    for (int ni = 0; ni < 4; ni++) {
        int cc = col0 + wn + ni * 8 + 2 * tg;
        if (cc >= Nc) continue;
        float bb0 = bias ? bias[cc] : 0.0f;
        float bb1 = bias ? bias[cc + 1] : 0.0f;
        float sc0 = 1.0f, sh0 = 0.0f, sc1 = 1.0f, sh1 = 0.0f;
        if (bn_relu) {
            sc0 = rsqrtf(var[cc] + EPSV) * gamma[cc];
            sh0 = beta[cc] - mean[cc] * sc0;
            sc1 = rsqrtf(var[cc + 1] + EPSV) * gamma[cc + 1];
            sh1 = beta[cc + 1] - mean[cc + 1] * sc1;
        }
#pragma unroll
        for (int mi = 0; mi < 2; mi++) {
#pragma unroll
            for (int half = 0; half < 2; half++) {
                int r = row0 + wm + mi * 16 + g + half * 8;
                if (r >= M) continue;
                float v0 = c[mi][ni][half * 2 + 0] + bb0;
                float v1 = c[mi][ni][half * 2 + 1] + bb1;
                if (bn_relu) {
                    v0 = fmaxf(0.0f, fmaf(v0, sc0, sh0));
                    v1 = fmaxf(0.0f, fmaf(v1, sc1, sh1));
                }
                if (Cf32) *(float2*)&Cf32[(size_t)r * Nc + cc] = make_float2(v0, v1);
                if (Cf16) {
                    __half2 hv = __floats2half2_rn(v0, v1);
                    *(uint32_t*)&Cf16[(size_t)r * Nc + cc] = *(uint32_t*)&hv;
                }
            }
        }
    }
}

// ---------------- launch ----------------
static inline int cdiv(long long a, long long b) { return (int)((a + b - 1) / b); }

extern "C" void kernel_launch(void* const* d_in, const int* in_sizes, int n_in,
                              void* d_out, int out_size) {
    const float* x = (const float*)d_in[0];
    const int* ei = (const int*)d_in[1];
    const float* W1 = (const float*)d_in[2];
    const float* b1 = (const float*)d_in[3];
    const float* g1 = (const float*)d_in[4];
    const float* be1 = (const float*)d_in[5];
    const float* m1 = (const float*)d_in[6];
    const float* v1 = (const float*)d_in[7];
    const float* W2 = (const float*)d_in[8];
    const float* b2 = (const float*)d_in[9];
    const float* g2 = (const float*)d_in[10];
    const float* be2 = (const float*)d_in[11];
    const float* m2 = (const float*)d_in[12];
    const float* v2 = (const float*)d_in[13];
    const float* W3 = (const float*)d_in[14];
    const float* b3 = (const float*)d_in[15];
    const int E = in_sizes[1] / 2;
    const int* src = ei;
    const int* dst = ei + E;

    float* out = (float*)d_out;
    const bool have_emb = out_size >= NN * (DOUTF + DH);
    float* emb = out + (size_t)NN * DOUTF;

    float *dinv, *selfn, *z3, *csr_w;
    int *cnt, *cur, *off, *blk, *csr_src;
    __half *fa, *fz;
    uint32_t *w1h, *w1l, *w2h, *w2l, *w3h, *w3l;
    cudaGetSymbolAddress((void**)&dinv, g_dinv);
    cudaGetSymbolAddress((void**)&selfn, g_selfn);
    cudaGetSymbolAddress((void**)&z3, g_z3);
    cudaGetSymbolAddress((void**)&cnt, g_cnt);
    cudaGetSymbolAddress((void**)&cur, g_cur);
    cudaGetSymbolAddress((void**)&off, g_off);
    cudaGetSymbolAddress((void**)&blk, g_blk);
    cudaGetSymbolAddress((void**)&csr_src, g_csr_src);
    cudaGetSymbolAddress((void**)&csr_w, g_csr_w);
    cudaGetSymbolAddress((void**)&fa, g_fa);
    cudaGetSymbolAddress((void**)&fz, g_fz);
    cudaGetSymbolAddress((void**)&w1h, g_w1h);
    cudaGetSymbolAddress((void**)&w1l, g_w1l);
    cudaGetSymbolAddress((void**)&w2h, g_w2h);
    cudaGetSymbolAddress((void**)&w2l, g_w2l);
    cudaGetSymbolAddress((void**)&w3h, g_w3h);
    cudaGetSymbolAddress((void**)&w3l, g_w3l);

    const int T = 256;

    // ---- CSR build ----
    k_zero_int<<<cdiv(NN, T), T>>>(cnt, NN);
    k_count_int<<<cdiv(E, T), T>>>(dst, E, cnt);
    k_norms_from_cnt<<<cdiv(NN, T), T>>>(cnt, dinv, selfn, NN);
    k_scan_block<<<NB_SCAN, 1024>>>(cnt, off, blk, NN);
    k_scan_top<<<1, 32>>>(blk, NB_SCAN);
    k_scan_add<<<cdiv(NN, T), T>>>(off, blk, NN, E);
    k_zero_int<<<cdiv(NN, T), T>>>(cur, NN);
    k_fill<<<cdiv(E, T), T>>>(src, dst, E, off, cur, dinv, csr_src, csr_w);

    // ---- weight splits + x conversion ----
    k_split_w<<<cdiv(DH * (DIN / 2), T), T>>>(W1, w1h, w1l, DIN, DH);
    k_split_w<<<cdiv(DH * (DH / 2), T), T>>>(W2, w2h, w2l, DH, DH);
    k_split_w<<<cdiv(DOUTF * (DH / 2), T), T>>>(W3, w3h, w3l, DH, DOUTF);
    k_f32_to_f16<<<cdiv((long long)NN * DIN / 2, T), T>>>((const float2*)x, (__half2*)fa,
                                                          NN * DIN / 2);

    dim3 gridH((DH + 63) / 64, (NN + 127) / 128);
    dim3 gridO(1, (NN + 127) / 128);

    // ---- layer 1: z1 = Agg(x16); h1 = relu(bn1(z1@W1+b1)) -> fa (fp16) ----
    k_gather_h2<DIN><<<NN, DIN / 2>>>(fa, fz, off, csr_src, csr_w, dinv, selfn);
    k_gemm_f16<<<gridH, 256>>>(fz, w1h, w1l, nullptr, fa, NN, DIN, DH, b1, g1, be1, m1, v1, 1);

    // ---- layer 2: z2 = Agg(h1); h2 = relu(bn2(z2@W2+b2)) -> emb fp32 + fa fp16 ----
    k_gather_h2<DH><<<NN, DH / 2>>>(fa, fz, off, csr_src, csr_w, dinv, selfn);
    k_gemm_f16<<<gridH, 256>>>(fz, w2h, w2l, have_emb ? emb : nullptr, fa,
                               NN, DH, DH, b2, g2, be2, m2, v2, 1);

    // ---- layer 3: z3 = h2@W3 (fp32); out = log_softmax(Agg(z3)+b3) ----
    k_gemm_f16<<<gridO, 256>>>(fa, w3h, w3l, z3, nullptr, NN, DH, DOUTF,
                               nullptr, nullptr, nullptr, nullptr, nullptr, 0);
    k_gather40_softmax<<<cdiv(NN, 8), 256>>>(z3, b3, out, off, csr_src, csr_w, dinv, selfn);
}

// round 12
// speedup vs baseline: 4.7196x; 1.2455x over previous
#include <cuda_runtime.h>
#include <cuda_fp16.h>
#include <math.h>
#include <stdint.h>

#define NN 169343
#define DIN 128
#define DH 256
#define DOUTF 40
#define EPSV 1e-5f
#define EMAX 2500000
#define NB_SCAN ((NN + 1023) / 1024)

// ---------------- scratch (static device globals) ----------------
__device__ __align__(128) float  g_dinv[NN];
__device__ __align__(128) float  g_selfn[NN];
__device__ __align__(128) int    g_cnt[NN];
__device__ __align__(128) int    g_cur[NN];
__device__ __align__(128) int    g_off[NN + 1];
__device__ __align__(128) int    g_blk[256];
__device__ __align__(128) int    g_csr_src[EMAX];
__device__ __align__(128) float  g_csr_w[EMAX];
__device__ __align__(128) __half g_fa[(size_t)NN * DH];   // feature table (x / h1 / h2)
__device__ __align__(128) __half g_fz[(size_t)NN * DH];   // aggregated table (z1 / z2)
__device__ __align__(128) float  g_z3[(size_t)NN * DOUTF];
// pre-split, pre-transposed, pre-paired weights: [Nc][K/2] u32 = {fp16(k), fp16(k+1)}
__device__ __align__(128) uint32_t g_w1h[DH * (DIN / 2)], g_w1l[DH * (DIN / 2)];
__device__ __align__(128) uint32_t g_w2h[DH * (DH / 2)],  g_w2l[DH * (DH / 2)];
__device__ __align__(128) uint32_t g_w3h[DOUTF * (DH / 2)], g_w3l[DOUTF * (DH / 2)];

// ---------------- CSR construction ----------------
__global__ void k_zero_int(int* __restrict__ p, int n) {
    int i = blockIdx.x * blockDim.x + threadIdx.x;
    if (i < n) p[i] = 0;
}
__global__ void k_count_int(const int* __restrict__ dst, int E, int* __restrict__ cnt) {
    int e = blockIdx.x * blockDim.x + threadIdx.x;
    if (e < E) atomicAdd(&cnt[dst[e]], 1);
}
__global__ __launch_bounds__(1024) void k_scan_block(const int* __restrict__ cnt,
                                                     int* __restrict__ off,
                                                     int* __restrict__ blk, int n) {
    __shared__ int s[1024];
    int t = threadIdx.x;
    int i = blockIdx.x * 1024 + t;
    int v = (i < n) ? cnt[i] : 0;
    s[t] = v;
    __syncthreads();
#pragma unroll
    for (int o = 1; o < 1024; o <<= 1) {
        int add = (t >= o) ? s[t - o] : 0;
        __syncthreads();
        s[t] += add;
        __syncthreads();
    }
    if (i <= n) off[i] = s[t] - v;
    if (t == 1023) blk[blockIdx.x] = s[1023];
}
__global__ void k_scan_top(int* __restrict__ blk, int nb) {
    if (threadIdx.x == 0 && blockIdx.x == 0) {
        int run = 0;
        for (int b = 0; b < nb; b++) { int v = blk[b]; blk[b] = run; run += v; }
    }
}
// fused: offset fixup + cur=0 + degree norms
__global__ void k_scan_add_norms(int* __restrict__ off, const int* __restrict__ blkv,
                                 const int* __restrict__ cnt, int* __restrict__ cur,
                                 float* __restrict__ dinv, float* __restrict__ selfn,
                                 int n, int E) {
    int i = blockIdx.x * blockDim.x + threadIdx.x;
    if (i < n) {
        off[i] += blkv[i / 1024];
        cur[i] = 0;
        float deg = (float)cnt[i] + 1.0f;
        dinv[i] = rsqrtf(deg);
        selfn[i] = 1.0f / deg;
    }
    if (i == 0) off[n] = E;
}
__global__ void k_fill(const int* __restrict__ src, const int* __restrict__ dst, int E,
                       const int* __restrict__ off, int* __restrict__ cur,
                       const float* __restrict__ dinv,
                       int* __restrict__ csr_src, float* __restrict__ csr_w) {
    int e = blockIdx.x * blockDim.x + threadIdx.x;
    if (e >= E) return;
    int d = dst[e];
    int s = src[e];
    int pos = off[d] + atomicAdd(&cur[d], 1);
    csr_src[pos] = s;
    csr_w[pos] = dinv[s];
}

// ---------------- fp32 -> fp16 convert (x table) ----------------
__global__ void k_f32_to_f16(const float2* __restrict__ in, __half2* __restrict__ out, int n2) {
    int i = blockIdx.x * blockDim.x + threadIdx.x;
    if (i < n2) {
        float2 v = in[i];
        out[i] = __floats2half2_rn(v.x, v.y);
    }
}

// ---------------- weight split: W[K][Nc] fp32 -> Wp_h/Wp_l [Nc][K/2] u32 (paired fp16) ----------
__global__ void k_split_w(const float* __restrict__ W, uint32_t* __restrict__ Wh,
                          uint32_t* __restrict__ Wl, int K, int Nc) {
    int idx = blockIdx.x * blockDim.x + threadIdx.x;
    int Kp = K / 2;
    if (idx >= Nc * Kp) return;
    int n = idx / Kp;
    int kp = idx - n * Kp;
    float w0 = W[(size_t)(2 * kp) * Nc + n];
    float w1 = W[(size_t)(2 * kp + 1) * Nc + n];
    __half h0 = __float2half_rn(w0), h1 = __float2half_rn(w1);
    __half l0 = __float2half_rn(w0 - __half2float(h0));
    __half l1 = __float2half_rn(w1 - __half2float(h1));
    __half2 H = __halves2half2(h0, h1), L = __halves2half2(l0, l1);
    Wh[idx] = *(uint32_t*)&H;
    Wl[idx] = *(uint32_t*)&L;
}

// ---------------- warp-per-node CSR gather (fp16 in/out, fp32 accum) ----------------
// lane owns F/32 contiguous halves; edge-unrolled x2
template <int F>
__global__ __launch_bounds__(256) void k_gather_warp(
    const __half* __restrict__ feat, __half* __restrict__ aggout,
    const int* __restrict__ off, const int* __restrict__ csr_src,
    const float* __restrict__ csr_w, const float* __restrict__ dinv,
    const float* __restrict__ selfn) {
    constexpr int VPL = F / 32;   // halves per lane (8 for 256, 4 for 128)
    constexpr int H2 = VPL / 2;   // half2 per lane
    int node = blockIdx.x * 8 + (threadIdx.x >> 5);
    int lane = threadIdx.x & 31;
    if (node >= NN) return;
    int beg = off[node], end = off[node + 1];

    float accx[H2], accy[H2];
#pragma unroll
    for (int i = 0; i < H2; i++) { accx[i] = 0.f; accy[i] = 0.f; }

    int e = beg;
    for (; e + 1 < end; e += 2) {
        int s0 = csr_src[e], s1 = csr_src[e + 1];
        float w0 = csr_w[e], w1 = csr_w[e + 1];
        uint32_t u0[H2], u1[H2];
        if (H2 == 4) {
            uint4 v0 = *(const uint4*)(feat + (size_t)s0 * F + lane * VPL);
            uint4 v1 = *(const uint4*)(feat + (size_t)s1 * F + lane * VPL);
            u0[0] = v0.x; u0[1] = v0.y; u0[2] = v0.z; u0[3] = v0.w;
            u1[0] = v1.x; u1[1] = v1.y; u1[2] = v1.z; u1[3] = v1.w;
        } else {
            uint2 v0 = *(const uint2*)(feat + (size_t)s0 * F + lane * VPL);
            uint2 v1 = *(const uint2*)(feat + (size_t)s1 * F + lane * VPL);
            u0[0] = v0.x; u0[1] = v0.y;
            u1[0] = v1.x; u1[1] = v1.y;
        }
#pragma unroll
        for (int i = 0; i < H2; i++) {
            float2 f0 = __half22float2(*(__half2*)&u0[i]);
            float2 f1 = __half22float2(*(__half2*)&u1[i]);
            accx[i] = fmaf(w0, f0.x, accx[i]); accy[i] = fmaf(w0, f0.y, accy[i]);
            accx[i] = fmaf(w1, f1.x, accx[i]); accy[i] = fmaf(w1, f1.y, accy[i]);
        }
    }
    if (e < end) {
        int s0 = csr_src[e];
        float w0 = csr_w[e];
        uint32_t u0[H2];
        if (H2 == 4) {
            uint4 v0 = *(const uint4*)(feat + (size_t)s0 * F + lane * VPL);
            u0[0] = v0.x; u0[1] = v0.y; u0[2] = v0.z; u0[3] = v0.w;
        } else {
            uint2 v0 = *(const uint2*)(feat + (size_t)s0 * F + lane * VPL);
            u0[0] = v0.x; u0[1] = v0.y;
        }
#pragma unroll
        for (int i = 0; i < H2; i++) {
            float2 f0 = __half22float2(*(__half2*)&u0[i]);
            accx[i] = fmaf(w0, f0.x, accx[i]); accy[i] = fmaf(w0, f0.y, accy[i]);
        }
    }

    // self-loop term + store
    float di = dinv[node], sn = selfn[node];
    uint32_t us[H2], ou[H2];
    if (H2 == 4) {
        uint4 v = *(const uint4*)(feat + (size_t)node * F + lane * VPL);
        us[0] = v.x; us[1] = v.y; us[2] = v.z; us[3] = v.w;
    } else {
        uint2 v = *(const uint2*)(feat + (size_t)node * F + lane * VPL);
        us[0] = v.x; us[1] = v.y;
    }
#pragma unroll
    for (int i = 0; i < H2; i++) {
        float2 fs = __half22float2(*(__half2*)&us[i]);
        __half2 r = __floats2half2_rn(fmaf(di, accx[i], sn * fs.x),
                                      fmaf(di, accy[i], sn * fs.y));
        ou[i] = *(uint32_t*)&r;
    }
    if (H2 == 4) {
        *(uint4*)(aggout + (size_t)node * F + lane * VPL) = make_uint4(ou[0], ou[1], ou[2], ou[3]);
    } else {
        *(uint2*)(aggout + (size_t)node * F + lane * VPL) = make_uint2(ou[0], ou[1]);
    }
}

// ---------------- fused layer-3 gather (+bias) + log_softmax ----------------
__global__ __launch_bounds__(256) void k_gather40_softmax(
    const float* __restrict__ z3, const float* __restrict__ b3,
    float* __restrict__ out,
    const int* __restrict__ off, const int* __restrict__ csr_src,
    const float* __restrict__ csr_w,
    const float* __restrict__ dinv, const float* __restrict__ selfn) {
    int node = blockIdx.x * 8 + (threadIdx.x >> 5);
    int lane = threadIdx.x & 31;
    if (node >= NN) return;
    int beg = off[node], end = off[node + 1];
    float aa = 0.f, ab = 0.f;
    int e = beg;
    for (; e + 1 < end; e += 2) {
        int s0 = csr_src[e], s1 = csr_src[e + 1];
        float w0 = csr_w[e], w1 = csr_w[e + 1];
        const float* f0 = z3 + (size_t)s0 * DOUTF;
        const float* f1 = z3 + (size_t)s1 * DOUTF;
        aa = fmaf(w0, f0[lane], aa);
        aa = fmaf(w1, f1[lane], aa);
        if (lane < 8) {
            ab = fmaf(w0, f0[32 + lane], ab);
            ab = fmaf(w1, f1[32 + lane], ab);
        }
    }
    if (e < end) {
        float w = csr_w[e];
        const float* fs = z3 + (size_t)csr_src[e] * DOUTF;
        aa = fmaf(w, fs[lane], aa);
        if (lane < 8) ab = fmaf(w, fs[32 + lane], ab);
    }
    float di = dinv[node], sn = selfn[node];
    const float* fz = z3 + (size_t)node * DOUTF;
    float a = fmaf(di, aa, fmaf(sn, fz[lane], b3[lane]));
    float b = (lane < 8) ? fmaf(di, ab, fmaf(sn, fz[32 + lane], b3[32 + lane])) : -3.402823e38f;
    float m = fmaxf(a, b);
#pragma unroll
    for (int o = 16; o; o >>= 1) m = fmaxf(m, __shfl_xor_sync(0xffffffffu, m, o));
    float s = expf(a - m) + ((lane < 8) ? expf(b - m) : 0.0f);
#pragma unroll
    for (int o = 16; o; o >>= 1) s += __shfl_xor_sync(0xffffffffu, s, o);
    float lse = m + logf(s);
    float* q = out + (size_t)node * DOUTF;
    q[lane] = a - lse;
    if (lane < 8) q[32 + lane] = b - lse;
}

// ---------------- fp16 MMA ----------------
__device__ __forceinline__ void mma_f16(float* c, const uint32_t* a, uint32_t b0, uint32_t b1) {
    asm volatile(
        "mma.sync.aligned.m16n8k16.row.col.f32.f16.f16.f32 "
        "{%0,%1,%2,%3}, {%4,%5,%6,%7}, {%8,%9}, {%0,%1,%2,%3};"
        : "+f"(c[0]), "+f"(c[1]), "+f"(c[2]), "+f"(c[3])
        : "r"(a[0]), "r"(a[1]), "r"(a[2]), "r"(a[3]), "r"(b0), "r"(b1));
}

// ---------------- tensor-core GEMM: A fp16, W split fp16 (2 MMAs/k16) ----------------
__global__ __launch_bounds__(256) void k_gemm_f16(
    const __half* __restrict__ A,
    const uint32_t* __restrict__ Bph, const uint32_t* __restrict__ Bpl,
    float* __restrict__ Cf32, __half* __restrict__ Cf16,
    int M, int K, int Nc,
    const float* __restrict__ bias,
    const float* __restrict__ gamma, const float* __restrict__ beta,
    const float* __restrict__ mean, const float* __restrict__ var,
    int bn_relu) {
    constexpr int BM = 128, BN = 64, BK = 32;
    constexpr int SP = 20;
    __shared__ uint32_t As[BM][SP];
    __shared__ uint32_t Bs_h[BN][SP], Bs_l[BN][SP];

    int tid = threadIdx.x;
    int lane = tid & 31;
    int wid = tid >> 5;
    int wm = (wid & 3) * 32;
    int wn = (wid >> 2) * 32;
    int row0 = blockIdx.y * BM;
    int col0 = blockIdx.x * BN;
    int g = lane >> 2;
    int tg = lane & 3;
    int Kp = K >> 1;

    float c[2][4][4];
#pragma unroll
    for (int mi = 0; mi < 2; mi++)
#pragma unroll
        for (int ni = 0; ni < 4; ni++)
#pragma unroll
            for (int r = 0; r < 4; r++) c[mi][ni][r] = 0.0f;

    for (int k0 = 0; k0 < K; k0 += BK) {
#pragma unroll
        for (int l = 0; l < 2; l++) {
            int idx = tid + l * 256;
            int m = idx >> 2;
            int q = idx & 3;
            int gr = row0 + m;
            uint4 v = make_uint4(0u, 0u, 0u, 0u);
            if (gr < M) v = *(const uint4*)(A + (size_t)gr * K + k0 + q * 8);
            As[m][q * 4 + 0] = v.x;
            As[m][q * 4 + 1] = v.y;
            As[m][q * 4 + 2] = v.z;
            As[m][q * 4 + 3] = v.w;
        }
#pragma unroll
        for (int l = 0; l < 4; l++) {
            int idx = tid + l * 256;
            int n = idx >> 4;
            int kp = idx & 15;
            int gc = col0 + n;
            uint32_t vh = 0u, vl = 0u;
            if (gc < Nc) {
                size_t o = (size_t)gc * Kp + (k0 >> 1) + kp;
                vh = Bph[o];
                vl = Bpl[o];
            }
            Bs_h[n][kp] = vh;
            Bs_l[n][kp] = vl;
        }
        __syncthreads();

#pragma unroll
        for (int ks = 0; ks < 2; ks++) {
            int kp0 = ks * 8;
            uint32_t a[2][4];
#pragma unroll
            for (int mi = 0; mi < 2; mi++) {
                int r = wm + mi * 16 + g;
                int cA = kp0 + tg;
                a[mi][0] = As[r][cA];
                a[mi][1] = As[r + 8][cA];
                a[mi][2] = As[r][cA + 4];
                a[mi][3] = As[r + 8][cA + 4];
            }
#pragma unroll
            for (int ni = 0; ni < 4; ni++) {
                int n = wn + ni * 8 + g;
                int cB = kp0 + tg;
                uint32_t bh0 = Bs_h[n][cB], bh1 = Bs_h[n][cB + 4];
                uint32_t bl0 = Bs_l[n][cB], bl1 = Bs_l[n][cB + 4];
#pragma unroll
                for (int mi = 0; mi < 2; mi++) {
                    mma_f16(c[mi][ni], a[mi], bh0, bh1);
                    mma_f16(c[mi][ni], a[mi], bl0, bl1);
                }
            }
        }
        __syncthreads();
    }

#pragma unroll
    for (int ni = 0; ni < 4; ni++) {
        int cc = col0 + wn + ni * 8 + 2 * tg;
        if (cc >= Nc) continue;
        float bb0 = bias ? bias[cc] : 0.0f;
        float bb1 = bias ? bias[cc + 1] : 0.0f;
        float sc0 = 1.0f, sh0 = 0.0f, sc1 = 1.0f, sh1 = 0.0f;
        if (bn_relu) {
            sc0 = rsqrtf(var[cc] + EPSV) * gamma[cc];
            sh0 = beta[cc] - mean[cc] * sc0;
            sc1 = rsqrtf(var[cc + 1] + EPSV) * gamma[cc + 1];
            sh1 = beta[cc + 1] - mean[cc + 1] * sc1;
        }
#pragma unroll
        for (int mi = 0; mi < 2; mi++) {
#pragma unroll
            for (int half = 0; half < 2; half++) {
                int r = row0 + wm + mi * 16 + g + half * 8;
                if (r >= M) continue;
                float v0 = c[mi][ni][half * 2 + 0] + bb0;
                float v1 = c[mi][ni][half * 2 + 1] + bb1;
                if (bn_relu) {
                    v0 = fmaxf(0.0f, fmaf(v0, sc0, sh0));
                    v1 = fmaxf(0.0f, fmaf(v1, sc1, sh1));
                }
                if (Cf32) *(float2*)&Cf32[(size_t)r * Nc + cc] = make_float2(v0, v1);
                if (Cf16) {
                    __half2 hv = __floats2half2_rn(v0, v1);
                    *(uint32_t*)&Cf16[(size_t)r * Nc + cc] = *(uint32_t*)&hv;
                }
            }
        }
    }
}

// ---------------- launch ----------------
static inline int cdiv(long long a, long long b) { return (int)((a + b - 1) / b); }

extern "C" void kernel_launch(void* const* d_in, const int* in_sizes, int n_in,
                              void* d_out, int out_size) {
    const float* x = (const float*)d_in[0];
    const int* ei = (const int*)d_in[1];
    const float* W1 = (const float*)d_in[2];
    const float* b1 = (const float*)d_in[3];
    const float* g1 = (const float*)d_in[4];
    const float* be1 = (const float*)d_in[5];
    const float* m1 = (const float*)d_in[6];
    const float* v1 = (const float*)d_in[7];
    const float* W2 = (const float*)d_in[8];
    const float* b2 = (const float*)d_in[9];
    const float* g2 = (const float*)d_in[10];
    const float* be2 = (const float*)d_in[11];
    const float* m2 = (const float*)d_in[12];
    const float* v2 = (const float*)d_in[13];
    const float* W3 = (const float*)d_in[14];
    const float* b3 = (const float*)d_in[15];
    const int E = in_sizes[1] / 2;
    const int* src = ei;
    const int* dst = ei + E;

    float* out = (float*)d_out;
    const bool have_emb = out_size >= NN * (DOUTF + DH);
    float* emb = out + (size_t)NN * DOUTF;

    float *dinv, *selfn, *z3, *csr_w;
    int *cnt, *cur, *off, *blk, *csr_src;
    __half *fa, *fz;
    uint32_t *w1h, *w1l, *w2h, *w2l, *w3h, *w3l;
    cudaGetSymbolAddress((void**)&dinv, g_dinv);
    cudaGetSymbolAddress((void**)&selfn, g_selfn);
    cudaGetSymbolAddress((void**)&z3, g_z3);
    cudaGetSymbolAddress((void**)&cnt, g_cnt);
    cudaGetSymbolAddress((void**)&cur, g_cur);
    cudaGetSymbolAddress((void**)&off, g_off);
    cudaGetSymbolAddress((void**)&blk, g_blk);
    cudaGetSymbolAddress((void**)&csr_src, g_csr_src);
    cudaGetSymbolAddress((void**)&csr_w, g_csr_w);
    cudaGetSymbolAddress((void**)&fa, g_fa);
    cudaGetSymbolAddress((void**)&fz, g_fz);
    cudaGetSymbolAddress((void**)&w1h, g_w1h);
    cudaGetSymbolAddress((void**)&w1l, g_w1l);
    cudaGetSymbolAddress((void**)&w2h, g_w2h);
    cudaGetSymbolAddress((void**)&w2l, g_w2l);
    cudaGetSymbolAddress((void**)&w3h, g_w3h);
    cudaGetSymbolAddress((void**)&w3l, g_w3l);

    const int T = 256;

    // ---- CSR build ----
    k_zero_int<<<cdiv(NN, T), T>>>(cnt, NN);
    k_count_int<<<cdiv(E, T), T>>>(dst, E, cnt);
    k_scan_block<<<NB_SCAN, 1024>>>(cnt, off, blk, NN);
    k_scan_top<<<1, 32>>>(blk, NB_SCAN);
    k_scan_add_norms<<<cdiv(NN, T), T>>>(off, blk, cnt, cur, dinv, selfn, NN, E);
    k_fill<<<cdiv(E, T), T>>>(src, dst, E, off, cur, dinv, csr_src, csr_w);

    // ---- weight splits + x conversion ----
    k_split_w<<<cdiv(DH * (DIN / 2), T), T>>>(W1, w1h, w1l, DIN, DH);
    k_split_w<<<cdiv(DH * (DH / 2), T), T>>>(W2, w2h, w2l, DH, DH);
    k_split_w<<<cdiv(DOUTF * (DH / 2), T), T>>>(W3, w3h, w3l, DH, DOUTF);
    k_f32_to_f16<<<cdiv((long long)NN * DIN / 2, T), T>>>((const float2*)x, (__half2*)fa,
                                                          NN * DIN / 2);

    dim3 gridH((DH + 63) / 64, (NN + 127) / 128);
    dim3 gridO(1, (NN + 127) / 128);

    // ---- layer 1: z1 = Agg(x16); h1 = relu(bn1(z1@W1+b1)) -> fa (fp16) ----
    k_gather_warp<DIN><<<cdiv(NN, 8), 256>>>(fa, fz, off, csr_src, csr_w, dinv, selfn);
    k_gemm_f16<<<gridH, 256>>>(fz, w1h, w1l, nullptr, fa, NN, DIN, DH, b1, g1, be1, m1, v1, 1);

    // ---- layer 2: z2 = Agg(h1); h2 = relu(bn2(z2@W2+b2)) -> emb fp32 + fa fp16 ----
    k_gather_warp<DH><<<cdiv(NN, 8), 256>>>(fa, fz, off, csr_src, csr_w, dinv, selfn);
    k_gemm_f16<<<gridH, 256>>>(fz, w2h, w2l, have_emb ? emb : nullptr, fa,
                               NN, DH, DH, b2, g2, be2, m2, v2, 1);

    // ---- layer 3: z3 = h2@W3 (fp32); out = log_softmax(Agg(z3)+b3) ----
    k_gemm_f16<<<gridO, 256>>>(fa, w3h, w3l, z3, nullptr, NN, DH, DOUTF,
                               nullptr, nullptr, nullptr, nullptr, nullptr, 0);
    k_gather40_softmax<<<cdiv(NN, 8), 256>>>(z3, b3, out, off, csr_src, csr_w, dinv, selfn);
}